// round 1
// baseline (speedup 1.0000x reference)
#include <cuda_runtime.h>

#define CIN 3
#define COUT 64
#define HH 512
#define WW 512
#define EE 3
#define TW 64
#define TH 8
#define NTHREADS 256

typedef unsigned long long ull;

__device__ __forceinline__ ull pk(float lo, float hi) {
    ull r;
    asm("mov.b64 %0, {%1,%2};" : "=l"(r) : "f"(lo), "f"(hi));
    return r;
}
__device__ __forceinline__ ull ffma2(ull a, ull b, ull c) {
    ull d;
    asm("fma.rn.f32x2 %0, %1, %2, %3;" : "=l"(d) : "l"(a), "l"(b), "l"(c));
    return d;
}
__device__ __forceinline__ ull fadd2(ull a, ull b) {
    ull d;
    asm("add.rn.f32x2 %0, %1, %2;" : "=l"(d) : "l"(a), "l"(b));
    return d;
}

__global__ void __launch_bounds__(NTHREADS, 2) conv_extra_kernel(
    const float* __restrict__ x,   // [8,3,512,512]
    const float* __restrict__ ei,  // [8,192]
    const float* __restrict__ wm,  // [64,3,3,3]
    const float* __restrict__ bm,  // [64]
    const float* __restrict__ we,  // [64,3,3,3]
    const float* __restrict__ be,  // [64]
    float* __restrict__ out)       // [8,64,512,512]
{
    // duplicated main-conv weights: per channel 28 tap-slots (27 real + 1 zero pad),
    // each slot is (w,w) packed in a 64-bit word. 14x 16B per channel -> LDS.128 friendly.
    __shared__ __align__(16) ull wpair[COUT * 28];
    __shared__ float xs[CIN][TH + 2][72];   // padded input patch, row stride 72 (16B aligned)
    __shared__ ull basePair[COUT];          // (base,base) per channel
    __shared__ float cT[COUT], cB[COUT], cL[COUT], cR[COUT];
    __shared__ float oTL[COUT], oTR[COUT], oBL[COUT], oBR[COUT];

    const int tid = threadIdx.x;
    const int tx = blockIdx.x, ty = blockIdx.y, b = blockIdx.z;
    const int w0 = tx * TW, h0 = ty * TH;

    // ---- stage duplicated weights ----
    {
        float* wf = (float*)wpair;
        for (int i = tid; i < COUT * 27; i += NTHREADS) {
            int c = i / 27, t = i - 27 * c;
            float v = wm[i];                 // wm linear [c][ci][ky][kx] == c*27 + t
            wf[(c * 28 + t) * 2 + 0] = v;
            wf[(c * 28 + t) * 2 + 1] = v;
        }
        if (tid < COUT) {
            wf[(tid * 28 + 27) * 2 + 0] = 0.f;
            wf[(tid * 28 + 27) * 2 + 1] = 0.f;
        }
    }

    // ---- stage input patch: rows h0-1..h0+TH, cols w0-1..w0+TW (zero padded) ----
    for (int i = tid; i < CIN * (TH + 2) * 66; i += NTHREADS) {
        int ci = i / ((TH + 2) * 66);
        int rem = i - ci * (TH + 2) * 66;
        int r = rem / 66, cc = rem - r * 66;
        int gh = h0 - 1 + r, gw = w0 - 1 + cc;
        float v = 0.f;
        if ((unsigned)gh < HH && (unsigned)gw < WW)
            v = x[((b * CIN + ci) * HH + gh) * WW + gw];
        xs[ci][r][cc] = v;
    }

    // ---- per-channel additive scalars for the "extra" term ----
    // M[c,e,h,w] = S_full minus excluded border rows/cols (+ corner overlap add-back)
    if (tid < COUT) {
        int c = tid;
        float S = 0, rT = 0, rB = 0, kL = 0, kR = 0;
        float tTL = 0, tTR = 0, tBL = 0, tBR = 0;
        #pragma unroll
        for (int e = 0; e < EE; e++) {
            float v = ei[b * (COUT * EE) + c * EE + e];
            const float* wp = we + (c * EE + e) * 9;
            #pragma unroll
            for (int ky = 0; ky < 3; ky++) {
                #pragma unroll
                for (int kx = 0; kx < 3; kx++) {
                    float t = v * wp[ky * 3 + kx];
                    S += t;
                    if (ky == 0) rT += t;
                    if (ky == 2) rB += t;
                    if (kx == 0) kL += t;
                    if (kx == 2) kR += t;
                    if (ky == 0 && kx == 0) tTL += t;
                    if (ky == 0 && kx == 2) tTR += t;
                    if (ky == 2 && kx == 0) tBL += t;
                    if (ky == 2 && kx == 2) tBR += t;
                }
            }
        }
        float base = bm[c] + be[c] + S;
        basePair[c] = pk(base, base);
        cT[c] = -rT; cB[c] = -rB; cL[c] = -kL; cR[c] = -kR;
        oTL[c] = tTL; oTR[c] = tTR; oBL[c] = tBL; oBR[c] = tBR;
    }
    __syncthreads();

    // ---- per-thread: 2 adjacent pixels (lane covers cols 2*lane, 2*lane+1), warp = 1 row ----
    const int lane = tid & 31, wrow = tid >> 5;
    const int px = lane * 2;
    const int h = h0 + wrow;
    const int gw0 = w0 + px;

    // build 27 packed (x_left, x_right) tap pairs once; reused across all 64 channels
    ull prl[27];
    #pragma unroll
    for (int ci = 0; ci < 3; ci++) {
        #pragma unroll
        for (int dy = 0; dy < 3; dy++) {
            const float* rp = &xs[ci][wrow + dy][px];
            float a0 = rp[0], a1 = rp[1], a2 = rp[2], a3 = rp[3];
            prl[ci * 9 + dy * 3 + 0] = pk(a0, a1);
            prl[ci * 9 + dy * 3 + 1] = pk(a1, a2);
            prl[ci * 9 + dy * 3 + 2] = pk(a2, a3);
        }
    }

    float* outp = out + (((size_t)b * COUT) * HH + h) * WW + gw0;
    const bool border = (tx == 0) | (tx == (WW / TW - 1)) | (ty == 0) | (ty == (HH / TH - 1));

    if (!border) {
        #pragma unroll 2
        for (int c = 0; c < COUT; c++) {
            const ulonglong2* wc = (const ulonglong2*)(wpair + c * 28);
            ull acc[3];
            acc[0] = basePair[c];
            acc[1] = 0ULL;
            acc[2] = 0ULL;
            #pragma unroll
            for (int q = 0; q < 13; q++) {
                ulonglong2 wv = wc[q];
                acc[(2 * q) % 3]     = ffma2(wv.x, prl[2 * q],     acc[(2 * q) % 3]);
                acc[(2 * q + 1) % 3] = ffma2(wv.y, prl[2 * q + 1], acc[(2 * q + 1) % 3]);
            }
            ull w26 = wpair[c * 28 + 26];
            acc[2] = ffma2(w26, prl[26], acc[2]);
            ull s = fadd2(acc[0], fadd2(acc[1], acc[2]));
            *(ull*)outp = s;
            outp += (size_t)HH * WW;
        }
    } else {
        // even column can only touch the left border; odd only the right.
        float mt = (h == 0) ? 1.f : 0.f;
        float mb = (h == HH - 1) ? 1.f : 0.f;
        float ml = (gw0 == 0) ? 1.f : 0.f;
        float mr = (gw0 + 1 == WW - 1) ? 1.f : 0.f;
        #pragma unroll 2
        for (int c = 0; c < COUT; c++) {
            const ulonglong2* wc = (const ulonglong2*)(wpair + c * 28);
            float basev = ((const float2*)basePair)[c].x;
            float srow = basev + mt * cT[c] + mb * cB[c];
            float s0 = srow + ml * (cL[c] + mt * oTL[c] + mb * oBL[c]);
            float s1 = srow + mr * (cR[c] + mt * oTR[c] + mb * oBR[c]);
            ull acc[3];
            acc[0] = pk(s0, s1);
            acc[1] = 0ULL;
            acc[2] = 0ULL;
            #pragma unroll
            for (int q = 0; q < 13; q++) {
                ulonglong2 wv = wc[q];
                acc[(2 * q) % 3]     = ffma2(wv.x, prl[2 * q],     acc[(2 * q) % 3]);
                acc[(2 * q + 1) % 3] = ffma2(wv.y, prl[2 * q + 1], acc[(2 * q + 1) % 3]);
            }
            ull w26 = wpair[c * 28 + 26];
            acc[2] = ffma2(w26, prl[26], acc[2]);
            ull s = fadd2(acc[0], fadd2(acc[1], acc[2]));
            *(ull*)outp = s;
            outp += (size_t)HH * WW;
        }
    }
}

extern "C" void kernel_launch(void* const* d_in, const int* in_sizes, int n_in,
                              void* d_out, int out_size)
{
    const float* x  = (const float*)d_in[0];
    const float* ei = (const float*)d_in[1];
    const float* wm = (const float*)d_in[2];
    const float* bm = (const float*)d_in[3];
    const float* we = (const float*)d_in[4];
    const float* be = (const float*)d_in[5];
    float* out = (float*)d_out;

    dim3 grid(WW / TW, HH / TH, 8);   // 8 x 64 x 8 = 4096 CTAs
    conv_extra_kernel<<<grid, NTHREADS>>>(x, ei, wm, bm, we, be, out);
}

// round 2
// speedup vs baseline: 1.2273x; 1.2273x over previous
#include <cuda_runtime.h>

#define CIN 3
#define COUT 64
#define HH 512
#define WW 512
#define EE 3
#define TW 64
#define TH 8
#define NTHREADS 256

typedef unsigned long long ull;

// duplicated (w,w) weight pairs, 64ch x 28 slots x 8B = 14336 B in the constant bank
__constant__ ull c_wpair[COUT * 28];
__device__ ull d_scratch[COUT * 28];

__device__ __forceinline__ ull pk(float lo, float hi) {
    ull r;
    asm("mov.b64 %0, {%1,%2};" : "=l"(r) : "f"(lo), "f"(hi));
    return r;
}
__device__ __forceinline__ ull ffma2(ull a, ull b, ull c) {
    ull d;
    asm("fma.rn.f32x2 %0, %1, %2, %3;" : "=l"(d) : "l"(a), "l"(b), "l"(c));
    return d;
}
__device__ __forceinline__ ull fadd2(ull a, ull b) {
    ull d;
    asm("add.rn.f32x2 %0, %1, %2;" : "=l"(d) : "l"(a), "l"(b));
    return d;
}

// duplicate weights into (w,w) pairs, zero-pad slot 27
__global__ void prep_weights(const float* __restrict__ wm) {
    int i = blockIdx.x * blockDim.x + threadIdx.x;
    float* sf = (float*)d_scratch;
    if (i < COUT * 27) {
        int c = i / 27, t = i - 27 * c;
        float v = wm[i];
        sf[(c * 28 + t) * 2 + 0] = v;
        sf[(c * 28 + t) * 2 + 1] = v;
    }
    if (i < COUT) {
        sf[(i * 28 + 27) * 2 + 0] = 0.f;
        sf[(i * 28 + 27) * 2 + 1] = 0.f;
    }
}

__global__ void __launch_bounds__(NTHREADS, 2) conv_extra_kernel(
    const float* __restrict__ x,   // [8,3,512,512]
    const float* __restrict__ ei,  // [8,192]
    const float* __restrict__ bm,  // [64]
    const float* __restrict__ we,  // [64,3,3,3]
    const float* __restrict__ be,  // [64]
    float* __restrict__ out)       // [8,64,512,512]
{
    __shared__ float xs[CIN][TH + 2][72];   // padded input patch, row stride 72 (16B aligned)
    __shared__ ull basePair[COUT];          // (base,base) per channel
    __shared__ float cT[COUT], cB[COUT], cL[COUT], cR[COUT];
    __shared__ float oTL[COUT], oTR[COUT], oBL[COUT], oBR[COUT];

    const int tid = threadIdx.x;
    const int tx = blockIdx.x, ty = blockIdx.y, b = blockIdx.z;
    const int w0 = tx * TW, h0 = ty * TH;

    // ---- stage input patch: rows h0-1..h0+TH, cols w0-1..w0+TW (zero padded) ----
    for (int i = tid; i < CIN * (TH + 2) * 66; i += NTHREADS) {
        int ci = i / ((TH + 2) * 66);
        int rem = i - ci * (TH + 2) * 66;
        int r = rem / 66, cc = rem - r * 66;
        int gh = h0 - 1 + r, gw = w0 - 1 + cc;
        float v = 0.f;
        if ((unsigned)gh < HH && (unsigned)gw < WW)
            v = x[((b * CIN + ci) * HH + gh) * WW + gw];
        xs[ci][r][cc] = v;
    }

    // ---- per-channel additive scalars for the "extra" term ----
    if (tid < COUT) {
        int c = tid;
        float S = 0, rT = 0, rB = 0, kL = 0, kR = 0;
        float tTL = 0, tTR = 0, tBL = 0, tBR = 0;
        #pragma unroll
        for (int e = 0; e < EE; e++) {
            float v = ei[b * (COUT * EE) + c * EE + e];
            const float* wp = we + (c * EE + e) * 9;
            #pragma unroll
            for (int ky = 0; ky < 3; ky++) {
                #pragma unroll
                for (int kx = 0; kx < 3; kx++) {
                    float t = v * wp[ky * 3 + kx];
                    S += t;
                    if (ky == 0) rT += t;
                    if (ky == 2) rB += t;
                    if (kx == 0) kL += t;
                    if (kx == 2) kR += t;
                    if (ky == 0 && kx == 0) tTL += t;
                    if (ky == 0 && kx == 2) tTR += t;
                    if (ky == 2 && kx == 0) tBL += t;
                    if (ky == 2 && kx == 2) tBR += t;
                }
            }
        }
        float base = bm[c] + be[c] + S;
        basePair[c] = pk(base, base);
        cT[c] = -rT; cB[c] = -rB; cL[c] = -kL; cR[c] = -kR;
        oTL[c] = tTL; oTR[c] = tTR; oBL[c] = tBL; oBR[c] = tBR;
    }
    __syncthreads();

    // ---- per-thread: 2 adjacent pixels (lane covers cols 2*lane, 2*lane+1), warp = 1 row ----
    const int lane = tid & 31, wrow = tid >> 5;
    const int px = lane * 2;
    const int h = h0 + wrow;
    const int gw0 = w0 + px;

    // build 27 packed (x_left, x_right) tap pairs once; reused across all 64 channels
    ull prl[27];
    #pragma unroll
    for (int ci = 0; ci < 3; ci++) {
        #pragma unroll
        for (int dy = 0; dy < 3; dy++) {
            const float* rp = &xs[ci][wrow + dy][px];
            float a0 = rp[0], a1 = rp[1], a2 = rp[2], a3 = rp[3];
            prl[ci * 9 + dy * 3 + 0] = pk(a0, a1);
            prl[ci * 9 + dy * 3 + 1] = pk(a1, a2);
            prl[ci * 9 + dy * 3 + 2] = pk(a2, a3);
        }
    }

    float* outp = out + (((size_t)b * COUT) * HH + h) * WW + gw0;
    const bool border = (tx == 0) | (tx == (WW / TW - 1)) | (ty == 0) | (ty == (HH / TH - 1));

    if (!border) {
        #pragma unroll 2
        for (int c = 0; c < COUT; c++) {
            const ulonglong2* wc = (const ulonglong2*)(c_wpair + c * 28);
            ull acc[3];
            acc[0] = basePair[c];
            acc[1] = 0ULL;
            acc[2] = 0ULL;
            #pragma unroll
            for (int q = 0; q < 13; q++) {
                ulonglong2 wv = wc[q];
                acc[(2 * q) % 3]     = ffma2(wv.x, prl[2 * q],     acc[(2 * q) % 3]);
                acc[(2 * q + 1) % 3] = ffma2(wv.y, prl[2 * q + 1], acc[(2 * q + 1) % 3]);
            }
            ull w26 = c_wpair[c * 28 + 26];
            acc[2] = ffma2(w26, prl[26], acc[2]);
            ull s = fadd2(acc[0], fadd2(acc[1], acc[2]));
            *(ull*)outp = s;
            outp += (size_t)HH * WW;
        }
    } else {
        // even column can only touch the left border; odd only the right.
        float mt = (h == 0) ? 1.f : 0.f;
        float mb = (h == HH - 1) ? 1.f : 0.f;
        float ml = (gw0 == 0) ? 1.f : 0.f;
        float mr = (gw0 + 1 == WW - 1) ? 1.f : 0.f;
        #pragma unroll 2
        for (int c = 0; c < COUT; c++) {
            const ulonglong2* wc = (const ulonglong2*)(c_wpair + c * 28);
            float basev = ((const float2*)basePair)[c].x;
            float srow = basev + mt * cT[c] + mb * cB[c];
            float s0 = srow + ml * (cL[c] + mt * oTL[c] + mb * oBL[c]);
            float s1 = srow + mr * (cR[c] + mt * oTR[c] + mb * oBR[c]);
            ull acc[3];
            acc[0] = pk(s0, s1);
            acc[1] = 0ULL;
            acc[2] = 0ULL;
            #pragma unroll
            for (int q = 0; q < 13; q++) {
                ulonglong2 wv = wc[q];
                acc[(2 * q) % 3]     = ffma2(wv.x, prl[2 * q],     acc[(2 * q) % 3]);
                acc[(2 * q + 1) % 3] = ffma2(wv.y, prl[2 * q + 1], acc[(2 * q + 1) % 3]);
            }
            ull w26 = c_wpair[c * 28 + 26];
            acc[2] = ffma2(w26, prl[26], acc[2]);
            ull s = fadd2(acc[0], fadd2(acc[1], acc[2]));
            *(ull*)outp = s;
            outp += (size_t)HH * WW;
        }
    }
}

extern "C" void kernel_launch(void* const* d_in, const int* in_sizes, int n_in,
                              void* d_out, int out_size)
{
    const float* x  = (const float*)d_in[0];
    const float* ei = (const float*)d_in[1];
    const float* wm = (const float*)d_in[2];
    const float* bm = (const float*)d_in[3];
    const float* we = (const float*)d_in[4];
    const float* be = (const float*)d_in[5];
    float* out = (float*)d_out;

    // 1) duplicate weights into (w,w) pairs in device scratch
    prep_weights<<<(COUT * 27 + 255) / 256, 256>>>(wm);

    // 2) copy scratch into the constant bank (D2D async memcpy — graph-capturable)
    void* scratch_ptr = nullptr;
    cudaGetSymbolAddress(&scratch_ptr, d_scratch);
    cudaMemcpyToSymbolAsync(c_wpair, scratch_ptr, sizeof(ull) * COUT * 28, 0,
                            cudaMemcpyDeviceToDevice, 0);

    // 3) main kernel
    dim3 grid(WW / TW, HH / TH, 8);   // 8 x 64 x 8 = 4096 CTAs
    conv_extra_kernel<<<grid, NTHREADS>>>(x, ei, bm, we, be, out);
}

// round 3
// speedup vs baseline: 1.3255x; 1.0800x over previous
#include <cuda_runtime.h>

#define CIN 3
#define COUT 64
#define HH 512
#define WW 512
#define EE 3
#define TW 64
#define TH 16
#define NTHREADS 256

typedef unsigned long long ull;

// duplicated (w,w) weight pairs, 64ch x 28 slots x 8B = 14336 B in the constant bank
__constant__ ull c_wpair[COUT * 28];
__device__ ull d_scratch[COUT * 28];

__device__ __forceinline__ ull pk(float lo, float hi) {
    ull r;
    asm("mov.b64 %0, {%1,%2};" : "=l"(r) : "f"(lo), "f"(hi));
    return r;
}
__device__ __forceinline__ ull ffma2(ull a, ull b, ull c) {
    ull d;
    asm("fma.rn.f32x2 %0, %1, %2, %3;" : "=l"(d) : "l"(a), "l"(b), "l"(c));
    return d;
}
__device__ __forceinline__ ull fadd2(ull a, ull b) {
    ull d;
    asm("add.rn.f32x2 %0, %1, %2;" : "=l"(d) : "l"(a), "l"(b));
    return d;
}

// duplicate weights into (w,w) pairs, zero-pad slot 27
__global__ void prep_weights(const float* __restrict__ wm) {
    int i = blockIdx.x * blockDim.x + threadIdx.x;
    float* sf = (float*)d_scratch;
    if (i < COUT * 27) {
        int c = i / 27, t = i - 27 * c;
        float v = wm[i];
        sf[(c * 28 + t) * 2 + 0] = v;
        sf[(c * 28 + t) * 2 + 1] = v;
    }
    if (i < COUT) {
        sf[(i * 28 + 27) * 2 + 0] = 0.f;
        sf[(i * 28 + 27) * 2 + 1] = 0.f;
    }
}

__global__ void __launch_bounds__(NTHREADS, 2) conv_extra_kernel(
    const float* __restrict__ x,   // [8,3,512,512]
    const float* __restrict__ ei,  // [8,192]
    const float* __restrict__ bm,  // [64]
    const float* __restrict__ we,  // [64,3,3,3]
    const float* __restrict__ be,  // [64]
    float* __restrict__ out)       // [8,64,512,512]
{
    __shared__ float xs[CIN][TH + 2][72];   // padded input patch, row stride 72 (16B aligned)
    __shared__ ull basePair[COUT];          // (base,base) per channel
    __shared__ float cT[COUT], cB[COUT], cL[COUT], cR[COUT];
    __shared__ float oTL[COUT], oTR[COUT], oBL[COUT], oBR[COUT];

    const int tid = threadIdx.x;
    const int tx = blockIdx.x, ty = blockIdx.y, b = blockIdx.z;
    const int w0 = tx * TW, h0 = ty * TH;

    // ---- stage input patch: rows h0-1..h0+TH, cols w0-1..w0+TW (zero padded) ----
    for (int i = tid; i < CIN * (TH + 2) * 66; i += NTHREADS) {
        int ci = i / ((TH + 2) * 66);
        int rem = i - ci * (TH + 2) * 66;
        int r = rem / 66, cc = rem - r * 66;
        int gh = h0 - 1 + r, gw = w0 - 1 + cc;
        float v = 0.f;
        if ((unsigned)gh < HH && (unsigned)gw < WW)
            v = x[((b * CIN + ci) * HH + gh) * WW + gw];
        xs[ci][r][cc] = v;
    }

    // ---- per-channel additive scalars for the "extra" term ----
    if (tid < COUT) {
        int c = tid;
        float S = 0, rT = 0, rB = 0, kL = 0, kR = 0;
        float tTL = 0, tTR = 0, tBL = 0, tBR = 0;
        #pragma unroll
        for (int e = 0; e < EE; e++) {
            float v = ei[b * (COUT * EE) + c * EE + e];
            const float* wp = we + (c * EE + e) * 9;
            #pragma unroll
            for (int ky = 0; ky < 3; ky++) {
                #pragma unroll
                for (int kx = 0; kx < 3; kx++) {
                    float t = v * wp[ky * 3 + kx];
                    S += t;
                    if (ky == 0) rT += t;
                    if (ky == 2) rB += t;
                    if (kx == 0) kL += t;
                    if (kx == 2) kR += t;
                    if (ky == 0 && kx == 0) tTL += t;
                    if (ky == 0 && kx == 2) tTR += t;
                    if (ky == 2 && kx == 0) tBL += t;
                    if (ky == 2 && kx == 2) tBR += t;
                }
            }
        }
        float base = bm[c] + be[c] + S;
        basePair[c] = pk(base, base);
        cT[c] = -rT; cB[c] = -rB; cL[c] = -kL; cR[c] = -kR;
        oTL[c] = tTL; oTR[c] = tTR; oBL[c] = tBL; oBR[c] = tBR;
    }
    __syncthreads();

    // ---- per-thread: 4 adjacent pixels; thread grid 16 cols x 16 rows ----
    const int tcol = tid & 15, trow = tid >> 4;
    const int px = tcol * 4;
    const int h = h0 + trow;
    const int gw0 = w0 + px;

    // 5 overlapping packed pairs per (ci,dy) row covering 4 outputs:
    // pairs over a0..a5: (a0,a1)(a1,a2)(a2,a3)(a3,a4)(a4,a5)
    // output pair A (px,px+1) uses idx 0,1,2 ; pair B (px+2,px+3) uses idx 2,3,4
    ull prl[9][5];
    #pragma unroll
    for (int ci = 0; ci < 3; ci++) {
        #pragma unroll
        for (int dy = 0; dy < 3; dy++) {
            const float* rp = &xs[ci][trow + dy][px];
            float a0 = rp[0], a1 = rp[1], a2 = rp[2], a3 = rp[3], a4 = rp[4], a5 = rp[5];
            int r = ci * 3 + dy;
            prl[r][0] = pk(a0, a1);
            prl[r][1] = pk(a1, a2);
            prl[r][2] = pk(a2, a3);
            prl[r][3] = pk(a3, a4);
            prl[r][4] = pk(a4, a5);
        }
    }

    float* outp = out + (((size_t)b * COUT) * HH + h) * WW + gw0;
    const bool border = (tx == 0) | (tx == (WW / TW - 1)) | (ty == 0) | (ty == (HH / TH - 1));

    if (!border) {
        #pragma unroll 2
        for (int c = 0; c < COUT; c++) {
            const ulonglong2* wc = (const ulonglong2*)(c_wpair + c * 28);
            ull base = basePair[c];
            ull a0 = base, a1 = 0ULL;     // accumulators for pixel pair A
            ull b0 = base, b1 = 0ULL;     // accumulators for pixel pair B
            #pragma unroll
            for (int q = 0; q < 13; q++) {
                ulonglong2 wv = wc[q];
                int t0 = 2 * q, t1 = 2 * q + 1;
                int r0 = t0 / 3, k0 = t0 % 3;
                int r1 = t1 / 3, k1 = t1 % 3;
                if (q & 1) {
                    a1 = ffma2(wv.x, prl[r0][k0],     a1);
                    b1 = ffma2(wv.x, prl[r0][k0 + 2], b1);
                    a0 = ffma2(wv.y, prl[r1][k1],     a0);
                    b0 = ffma2(wv.y, prl[r1][k1 + 2], b0);
                } else {
                    a0 = ffma2(wv.x, prl[r0][k0],     a0);
                    b0 = ffma2(wv.x, prl[r0][k0 + 2], b0);
                    a1 = ffma2(wv.y, prl[r1][k1],     a1);
                    b1 = ffma2(wv.y, prl[r1][k1 + 2], b1);
                }
            }
            ull w26 = c_wpair[c * 28 + 26];
            a1 = ffma2(w26, prl[8][2], a1);
            b1 = ffma2(w26, prl[8][4], b1);
            ulonglong2 res;
            res.x = fadd2(a0, a1);
            res.y = fadd2(b0, b1);
            *(ulonglong2*)outp = res;
            outp += (size_t)HH * WW;
        }
    } else {
        float mt = (h == 0) ? 1.f : 0.f;
        float mb = (h == HH - 1) ? 1.f : 0.f;
        float ml = (gw0 == 0) ? 1.f : 0.f;          // only pixel 0 can touch left edge
        float mr = (gw0 + 3 == WW - 1) ? 1.f : 0.f; // only pixel 3 can touch right edge
        #pragma unroll 2
        for (int c = 0; c < COUT; c++) {
            const ulonglong2* wc = (const ulonglong2*)(c_wpair + c * 28);
            float basev = ((const float2*)basePair)[c].x;
            float srow = basev + mt * cT[c] + mb * cB[c];
            float s0 = srow + ml * (cL[c] + mt * oTL[c] + mb * oBL[c]);
            float s3 = srow + mr * (cR[c] + mt * oTR[c] + mb * oBR[c]);
            ull a0 = pk(s0, srow), a1 = 0ULL;
            ull b0 = pk(srow, s3), b1 = 0ULL;
            #pragma unroll
            for (int q = 0; q < 13; q++) {
                ulonglong2 wv = wc[q];
                int t0 = 2 * q, t1 = 2 * q + 1;
                int r0 = t0 / 3, k0 = t0 % 3;
                int r1 = t1 / 3, k1 = t1 % 3;
                if (q & 1) {
                    a1 = ffma2(wv.x, prl[r0][k0],     a1);
                    b1 = ffma2(wv.x, prl[r0][k0 + 2], b1);
                    a0 = ffma2(wv.y, prl[r1][k1],     a0);
                    b0 = ffma2(wv.y, prl[r1][k1 + 2], b0);
                } else {
                    a0 = ffma2(wv.x, prl[r0][k0],     a0);
                    b0 = ffma2(wv.x, prl[r0][k0 + 2], b0);
                    a1 = ffma2(wv.y, prl[r1][k1],     a1);
                    b1 = ffma2(wv.y, prl[r1][k1 + 2], b1);
                }
            }
            ull w26 = c_wpair[c * 28 + 26];
            a1 = ffma2(w26, prl[8][2], a1);
            b1 = ffma2(w26, prl[8][4], b1);
            ulonglong2 res;
            res.x = fadd2(a0, a1);
            res.y = fadd2(b0, b1);
            *(ulonglong2*)outp = res;
            outp += (size_t)HH * WW;
        }
    }
}

extern "C" void kernel_launch(void* const* d_in, const int* in_sizes, int n_in,
                              void* d_out, int out_size)
{
    const float* x  = (const float*)d_in[0];
    const float* ei = (const float*)d_in[1];
    const float* wm = (const float*)d_in[2];
    const float* bm = (const float*)d_in[3];
    const float* we = (const float*)d_in[4];
    const float* be = (const float*)d_in[5];
    float* out = (float*)d_out;

    prep_weights<<<(COUT * 27 + 255) / 256, 256>>>(wm);

    void* scratch_ptr = nullptr;
    cudaGetSymbolAddress(&scratch_ptr, d_scratch);
    cudaMemcpyToSymbolAsync(c_wpair, scratch_ptr, sizeof(ull) * COUT * 28, 0,
                            cudaMemcpyDeviceToDevice, 0);

    dim3 grid(WW / TW, HH / TH, 8);   // 8 x 32 x 8 = 2048 CTAs
    conv_extra_kernel<<<grid, NTHREADS>>>(x, ei, bm, we, be, out);
}